// round 4
// baseline (speedup 1.0000x reference)
#include <cuda_runtime.h>
#include <cstddef>

#define TT 8192
#define NT 1024
#define EE 8    // elements per thread (TT / NT)
#define NW (NT / 32)

__device__ __forceinline__ float tanh_approx(float x) {
    float y;
    asm("tanh.approx.f32 %0, %1;" : "=f"(y) : "f"(x));
    return y;
}
// sigmoid(0.01*p) via tanh identity: 1 MUFU instead of 2 dependent ones
__device__ __forceinline__ float sigmoid01(float p) {
    return fmaf(0.5f, tanh_approx(0.005f * p), 0.5f);
}
__device__ __forceinline__ float softplus_f(float z) {
    return __logf(1.f + __expf(z));
}

__global__ __launch_bounds__(NT, 1)
void voltage_kernel(const float* __restrict__ X, const float* __restrict__ SC,
                    const float* __restrict__ W1, const float* __restrict__ b1,
                    const float* __restrict__ W2, const float* __restrict__ b2,
                    float* __restrict__ out)
{
    __shared__ float sRed[NW];
    __shared__ float sA[NW];
    __shared__ float sB[NW];
    __shared__ float sLastT[NT];   // each thread's t[EE-1]
    __shared__ float sLastI[NT];   // each thread's I[EE-1]
    __shared__ float sFirstI[NT];  // each thread's I[0]
    __shared__ float sWf[40];      // folded weights: w10|c1r|w20|w21|w25|w26|b2x4
    __shared__ float sTmean;
    __shared__ float sU10;

    const int b    = blockIdx.x;
    const int tid  = threadIdx.x;
    const int lane = tid & 31;
    const int wid  = tid >> 5;
    const int cs   = tid * EE;
    const float* __restrict__ Xb = X + (size_t)b * TT * 3;

    // ---------- phase 1: vectorized chunk load (6 x LDG.128 per thread) ----------
    float tA[EE], IA[EE];
    float tsum = 0.f;
    {
        const float4* __restrict__ p4 =
            reinterpret_cast<const float4*>(Xb + (size_t)cs * 3);
        float4 v[6];
        #pragma unroll
        for (int k = 0; k < 6; ++k) v[k] = __ldg(p4 + k);
        #pragma unroll
        for (int g = 0; g < 2; ++g) {
            float4 a0 = v[3 * g + 0], a1 = v[3 * g + 1], a2 = v[3 * g + 2];
            tA[4 * g + 0] = a0.x; IA[4 * g + 0] = a0.y; tsum += a0.z;
            tA[4 * g + 1] = a0.w; IA[4 * g + 1] = a1.x; tsum += a1.y;
            tA[4 * g + 2] = a1.z; IA[4 * g + 2] = a1.w; tsum += a2.x;
            tA[4 * g + 3] = a2.y; IA[4 * g + 3] = a2.z; tsum += a2.w;
        }
    }
    sLastT[tid]  = tA[EE - 1];
    sLastI[tid]  = IA[EE - 1];
    sFirstI[tid] = IA[0];

    // block reduce for Tmean
    #pragma unroll
    for (int o = 16; o > 0; o >>= 1) tsum += __shfl_down_sync(0xffffffffu, tsum, o);
    if (lane == 0) sRed[wid] = tsum;
    __syncthreads();
    if (tid < 32) {
        float v = sRed[tid];
        #pragma unroll
        for (int o = 16; o > 0; o >>= 1) v += __shfl_down_sync(0xffffffffu, v, o);
        if (tid == 0) sTmean = v * (1.f / (float)TT);
    }
    __syncthreads();
    const float Tmean = sTmean;
    const float Q  = __ldg(SC + 2 * b + 0);
    const float R0 = __ldg(SC + 2 * b + 1);

    // fold per-batch-constant MLP inputs into shared weights (6 threads)
    if (tid < 6) {
        const int j = tid;
        sWf[j]      = __ldg(W1 + j);                                    // w10
        sWf[6 + j]  = fmaf(R0, __ldg(W1 + 6 + j),
                      fmaf(Tmean, __ldg(W1 + 12 + j), __ldg(b1 + j)));  // c1r
        sWf[12 + j] = __ldg(W2 + j * 7 + 0);                            // w20
        sWf[18 + j] = __ldg(W2 + j * 7 + 1);                            // w21
        sWf[24 + j] = __ldg(W2 + j * 7 + 5);                            // w25
        sWf[30 + j] = __ldg(W2 + j * 7 + 6);                            // w26
        if (j < 2) sWf[36 + j]     = __ldg(b2 + j);                     // b20,b21
        if (j >= 4) sWf[36 + j - 2] = __ldg(b2 + j + 1);                // b25,b26
    }

    // ---------- phase 2: per-thread local dSOC prefix (registers only) ----------
    float mA[EE];              // holds soc now; overwritten with base later
    float run = 0.f;
    {
        const float tprev = (tid > 0) ? sLastT[tid - 1] : 0.f;
        const float Iprev = (tid > 0) ? sLastI[tid - 1] : 0.f;
        if (tid > 0)
            run = (IA[0] + Iprev) * (tA[0] - tprev) * (1.f / 36000.f);
        mA[0] = run;
        #pragma unroll
        for (int e = 1; e < EE; ++e) {
            run += (IA[e] + IA[e - 1]) * (tA[e] - tA[e - 1]) * (1.f / 36000.f);
            mA[e] = run;
        }
    }
    // exclusive block scan of thread totals
    float inc = run;
    #pragma unroll
    for (int o = 1; o < 32; o <<= 1) {
        float y = __shfl_up_sync(0xffffffffu, inc, o);
        if (lane >= o) inc += y;
    }
    if (lane == 31) sRed[wid] = inc;
    __syncthreads();
    if (tid < 32) {
        float v = sRed[tid];
        #pragma unroll
        for (int o = 1; o < 32; o <<= 1) {
            float y = __shfl_up_sync(0xffffffffu, v, o);
            if (lane >= o) v += y;
        }
        sRed[tid] = v;   // inclusive warp totals
    }
    __syncthreads();
    const float warpOff = (wid > 0) ? sRed[wid - 1] : 0.f;
    const float socBase = Q * 0.2f + warpOff + (inc - run);
    const float Inext = (tid < NT - 1) ? sFirstI[tid + 1] : 0.f;

    // ---------- phase 3: fully-unrolled MLP + OCV + affine transition ----------
    float aA[EE], bA[EE];
    float At = 1.f, Bt = 0.f;
    #pragma unroll
    for (int e = 0; e < EE; ++e) {
        float soc = socBase + mA[e];

        float h[6];
        #pragma unroll
        for (int j = 0; j < 6; ++j)
            h[j] = softplus_f(fmaf(soc, sWf[j], sWf[6 + j]));

        float p0 = sWf[36], p1 = sWf[37], p5 = sWf[38], p6 = sWf[39];
        #pragma unroll
        for (int j = 0; j < 6; ++j) {
            p0 = fmaf(h[j], sWf[12 + j], p0);
            p1 = fmaf(h[j], sWf[18 + j], p1);
            p5 = fmaf(h[j], sWf[24 + j], p5);
            p6 = fmaf(h[j], sWf[30 + j], p6);
        }
        float R1 = 0.04f * sigmoid01(p0);
        float C  = 1e-6f * sigmoid01(p1);
        float xx = fmaf(0.79764f, sigmoid01(p5), 0.04236f);
        float yy = fmaf(0.82504f, sigmoid01(p6), 0.023f);

        float Up = fmaf(fmaf(fmaf(fmaf(fmaf(-2.2166f, yy, 3.5146f), yy, -2.0843f),
                                 yy, 1.6225f), yy, -1.6518f), yy, 4.4167f)
                 - 4.f * __expf(fmaf(109.451f, yy, -100.006f));
        float Un = 0.063f + 0.8f * __expf(-75.f * (xx + 0.001f))
                 - 0.012f  * tanh_approx((xx - 0.127f) * 62.5f)
                 - 0.0118f * tanh_approx((xx - 0.155f) * 62.5f)
                 - 0.0035f * tanh_approx((xx - 0.22f)  * 50.f)
                 - 0.0095f * tanh_approx((xx - 0.19f)  * 76.923076923f)
                 - 0.0145f * tanh_approx((xx - 0.49f)  * 50.f)
                 - 0.08f   * tanh_approx((xx - 1.03f)  * 18.18181818f);

        float Ii = IA[e];
        if (e == 0 && tid == 0) {
            float p2 = __ldg(b2 + 2);
            #pragma unroll
            for (int j = 0; j < 6; ++j) p2 = fmaf(h[j], __ldg(W2 + j * 7 + 2), p2);
            float OCV_U = fmaf(0.75f, sigmoid01(p2), 0.05f);
            sU10 = -OCV_U - Ii * R0;
        }
        mA[e] = fmaf(Ii, R0, Up - Un);   // overwrite soc with base voltage

        float In1 = (e < EE - 1) ? IA[e + 1] : Inext;
        bool last = (tid == NT - 1) && (e == EE - 1);
        float eps = (In1 - Ii) * C;      // dt = diff of I (per reference)
        float a  = last ? 1.f : 1.f - eps;
        float bb = last ? 0.f : eps * R1 * Ii;
        aA[e] = a; bA[e] = bb;
        Bt = fmaf(a, Bt, bb);
        At = a * At;
    }

    // ---------- phase 4: block affine-pair scan (exclusive) ----------
    float Ai = At, Bi = Bt;
    #pragma unroll
    for (int o = 1; o < 32; o <<= 1) {
        float pA = __shfl_up_sync(0xffffffffu, Ai, o);
        float pB = __shfl_up_sync(0xffffffffu, Bi, o);
        if (lane >= o) { Bi = fmaf(Ai, pB, Bi); Ai = Ai * pA; }
    }
    if (lane == 31) { sA[wid] = Ai; sB[wid] = Bi; }
    __syncthreads();
    if (tid < 32) {
        float vA = sA[tid];
        float vB = sB[tid];
        #pragma unroll
        for (int o = 1; o < 32; o <<= 1) {
            float pA = __shfl_up_sync(0xffffffffu, vA, o);
            float pB = __shfl_up_sync(0xffffffffu, vB, o);
            if (lane >= o) { vB = fmaf(vA, pB, vB); vA = vA * pA; }
        }
        sA[tid] = vA; sB[tid] = vB;
    }
    __syncthreads();
    float offA = 1.f, offB = 0.f;
    if (wid > 0) { offA = sA[wid - 1]; offB = sB[wid - 1]; }
    float eA = __shfl_up_sync(0xffffffffu, Ai, 1);
    float eB = __shfl_up_sync(0xffffffffu, Bi, 1);
    if (lane == 0) { eA = 1.f; eB = 0.f; }
    float GA = eA * offA;
    float GB = fmaf(eA, offB, eB);
    float U1 = fmaf(GA, sU10, GB);

    // ---------- phase 5: emit with float4 stores ----------
    float4* __restrict__ o4 = reinterpret_cast<float4*>(out + (size_t)b * TT + cs);
    #pragma unroll
    for (int g = 0; g < 2; ++g) {
        float4 w;
        w.x = mA[4 * g + 0] + U1;  U1 = fmaf(aA[4 * g + 0], U1, bA[4 * g + 0]);
        w.y = mA[4 * g + 1] + U1;  U1 = fmaf(aA[4 * g + 1], U1, bA[4 * g + 1]);
        w.z = mA[4 * g + 2] + U1;  U1 = fmaf(aA[4 * g + 2], U1, bA[4 * g + 2]);
        w.w = mA[4 * g + 3] + U1;  U1 = fmaf(aA[4 * g + 3], U1, bA[4 * g + 3]);
        o4[g] = w;
    }
}

extern "C" void kernel_launch(void* const* d_in, const int* in_sizes, int n_in,
                              void* d_out, int out_size)
{
    const float* X  = (const float*)d_in[0];
    const float* SC = (const float*)d_in[1];
    const float* W1 = (const float*)d_in[2];
    const float* b1 = (const float*)d_in[3];
    const float* W2 = (const float*)d_in[4];
    const float* b2 = (const float*)d_in[5];
    float* out = (float*)d_out;

    int B = in_sizes[1] / 2;   // SC is (B, 2)
    voltage_kernel<<<B, NT>>>(X, SC, W1, b1, W2, b2, out);
}

// round 5
// speedup vs baseline: 1.1793x; 1.1793x over previous
#include <cuda_runtime.h>
#include <cstddef>

#define TT 8192
#define NT 1024
#define EE 8    // elements per thread
#define NW 32   // warps per block

#define SMEM_BYTES ((4 * TT + NT) * 4)

__device__ __forceinline__ float tanh_approx(float x) {
    float y;
    asm("tanh.approx.f32 %0, %1;" : "=f"(y) : "f"(x));
    return y;
}
__device__ __forceinline__ float sigmoid01(float p) {
    return fmaf(0.5f, tanh_approx(0.005f * p), 0.5f);
}
__device__ __forceinline__ float softplus_f(float z) {
    return __logf(1.f + __expf(z));
}

__global__ __launch_bounds__(NT, 1)
void voltage_kernel(const float* __restrict__ X, const float* __restrict__ SC,
                    const float* __restrict__ W1, const float* __restrict__ b1,
                    const float* __restrict__ W2, const float* __restrict__ b2,
                    float* __restrict__ out)
{
    extern __shared__ float dsm[];
    float* __restrict__ sM  = dsm;            // [EE][NT]: soc local prefix -> base voltage
    float* __restrict__ sPA = dsm + TT;       // [EE][NT]: intra-thread exclusive affine A
    float* __restrict__ sPB = dsm + 2 * TT;   // [EE][NT]: intra-thread exclusive affine B
    float* __restrict__ sIv = dsm + 3 * TT;   // [EE][NT]: I values
    float* __restrict__ sLT = dsm + 4 * TT;   // [NT]: each thread's t[EE-1]

    __shared__ float sRed[NW], sA[NW], sB[NW];
    __shared__ float sW1f[12];   // w10[6] | c1r[6]
    __shared__ float sW2[24];    // w20 | w21 | w25 | w26
    __shared__ float sB2[4];     // b20 b21 b25 b26
    __shared__ float sTmean, sU10;

    const int b    = blockIdx.x;
    const int tid  = threadIdx.x;
    const int lane = tid & 31;
    const int wid  = tid >> 5;
    const float* __restrict__ Xb = X + (size_t)b * TT * 3;

    // ---------- phase 1: vector load, scatter I to smem, local trapezoid prefix ----------
    float tsum = 0.f, ppTot = 0.f, t0;
    {
        const float4* __restrict__ p4 =
            reinterpret_cast<const float4*>(Xb + (size_t)(tid * EE) * 3);
        float4 v0 = __ldg(p4 + 0), v1 = __ldg(p4 + 1), v2 = __ldg(p4 + 2);
        float4 v3 = __ldg(p4 + 3), v4 = __ldg(p4 + 4), v5 = __ldg(p4 + 5);
        float tA[EE], IA[EE];
        tA[0]=v0.x; IA[0]=v0.y; tsum+=v0.z;
        tA[1]=v0.w; IA[1]=v1.x; tsum+=v1.y;
        tA[2]=v1.z; IA[2]=v1.w; tsum+=v2.x;
        tA[3]=v2.y; IA[3]=v2.z; tsum+=v2.w;
        tA[4]=v3.x; IA[4]=v3.y; tsum+=v3.z;
        tA[5]=v3.w; IA[5]=v4.x; tsum+=v4.y;
        tA[6]=v4.z; IA[6]=v4.w; tsum+=v5.x;
        tA[7]=v5.y; IA[7]=v5.z; tsum+=v5.w;
        t0 = tA[0];
        sM[tid]  = 0.f;
        sIv[tid] = IA[0];
        #pragma unroll
        for (int e = 1; e < EE; ++e) {
            ppTot += (IA[e] + IA[e - 1]) * (tA[e] - tA[e - 1]) * (1.f / 36000.f);
            sM[e * NT + tid]  = ppTot;
            sIv[e * NT + tid] = IA[e];
        }
        sLT[tid] = tA[EE - 1];
    }

    // ---------- Tmean block reduce ----------
    #pragma unroll
    for (int o = 16; o > 0; o >>= 1) tsum += __shfl_down_sync(0xffffffffu, tsum, o);
    if (lane == 0) sRed[wid] = tsum;
    __syncthreads();
    if (tid < 32) {
        float v = sRed[tid];
        #pragma unroll
        for (int o = 16; o > 0; o >>= 1) v += __shfl_down_sync(0xffffffffu, v, o);
        if (tid == 0) sTmean = v * (1.f / (float)TT);
    }
    __syncthreads();
    const float Tmean = sTmean;
    const float Q  = __ldg(SC + 2 * b + 0);
    const float R0 = __ldg(SC + 2 * b + 1);

    // fold per-batch constants into shared weights (6 threads; read after later syncs)
    if (tid < 6) {
        const int j = tid;
        sW1f[j]     = __ldg(W1 + j);
        sW1f[6 + j] = fmaf(R0, __ldg(W1 + 6 + j),
                      fmaf(Tmean, __ldg(W1 + 12 + j), __ldg(b1 + j)));
        sW2[j]      = __ldg(W2 + j * 7 + 0);
        sW2[6 + j]  = __ldg(W2 + j * 7 + 1);
        sW2[12 + j] = __ldg(W2 + j * 7 + 5);
        sW2[18 + j] = __ldg(W2 + j * 7 + 6);
        if (j == 0) { sB2[0] = __ldg(b2 + 0); sB2[1] = __ldg(b2 + 1);
                      sB2[2] = __ldg(b2 + 5); sB2[3] = __ldg(b2 + 6); }
    }

    // ---------- phase 2: boundary term + block scan of thread SOC totals ----------
    float bnd = 0.f;
    if (tid > 0) {
        float tprev = sLT[tid - 1];
        float Iprev = sIv[(EE - 1) * NT + tid - 1];
        bnd = (sIv[tid] + Iprev) * (t0 - tprev) * (1.f / 36000.f);
    }
    const float run = ppTot + bnd;
    float inc = run;
    #pragma unroll
    for (int o = 1; o < 32; o <<= 1) {
        float y = __shfl_up_sync(0xffffffffu, inc, o);
        if (lane >= o) inc += y;
    }
    if (lane == 31) sRed[wid] = inc;
    __syncthreads();
    if (tid < 32) {
        float v = sRed[tid];
        #pragma unroll
        for (int o = 1; o < 32; o <<= 1) {
            float y = __shfl_up_sync(0xffffffffu, v, o);
            if (lane >= o) v += y;
        }
        sRed[tid] = v;
    }
    __syncthreads();
    const float warpOff = (wid > 0) ? sRed[wid - 1] : 0.f;
    const float socBase = Q * 0.2f + warpOff + (inc - run) + bnd;

    // register-resident first-layer weights (hot every element)
    float w10[6], c1r[6];
    #pragma unroll
    for (int j = 0; j < 6; ++j) { w10[j] = sW1f[j]; c1r[j] = sW1f[6 + j]; }

    // ---------- phase 3: MLP + OCV + affine prefix (state in smem) ----------
    float At = 1.f, Bt = 0.f;
    #pragma unroll
    for (int e = 0; e < EE; ++e) {
        float soc = socBase + sM[e * NT + tid];

        float h[6];
        #pragma unroll
        for (int j = 0; j < 6; ++j)
            h[j] = softplus_f(fmaf(soc, w10[j], c1r[j]));

        float p0 = sB2[0], p1 = sB2[1], p5 = sB2[2], p6 = sB2[3];
        #pragma unroll
        for (int j = 0; j < 6; ++j) {
            p0 = fmaf(h[j], sW2[j],      p0);
            p1 = fmaf(h[j], sW2[6 + j],  p1);
            p5 = fmaf(h[j], sW2[12 + j], p5);
            p6 = fmaf(h[j], sW2[18 + j], p6);
        }
        float R1 = 0.04f * sigmoid01(p0);
        float C  = 1e-6f * sigmoid01(p1);
        float xx = fmaf(0.79764f, sigmoid01(p5), 0.04236f);
        float yy = fmaf(0.82504f, sigmoid01(p6), 0.023f);

        float Up = fmaf(fmaf(fmaf(fmaf(fmaf(-2.2166f, yy, 3.5146f), yy, -2.0843f),
                                 yy, 1.6225f), yy, -1.6518f), yy, 4.4167f)
                 - 4.f * __expf(fmaf(109.451f, yy, -100.006f));
        float Un = 0.063f + 0.8f * __expf(-75.f * (xx + 0.001f))
                 - 0.012f  * tanh_approx((xx - 0.127f) * 62.5f)
                 - 0.0118f * tanh_approx((xx - 0.155f) * 62.5f)
                 - 0.0035f * tanh_approx((xx - 0.22f)  * 50.f)
                 - 0.0095f * tanh_approx((xx - 0.19f)  * 76.923076923f)
                 - 0.0145f * tanh_approx((xx - 0.49f)  * 50.f)
                 - 0.08f   * tanh_approx((xx - 1.03f)  * 18.18181818f);

        float Ii = sIv[e * NT + tid];
        if (e == 0 && tid == 0) {
            float p2 = __ldg(b2 + 2);
            #pragma unroll
            for (int j = 0; j < 6; ++j) p2 = fmaf(h[j], __ldg(W2 + j * 7 + 2), p2);
            float OCV_U = fmaf(0.75f, sigmoid01(p2), 0.05f);
            sU10 = -OCV_U - Ii * R0;
        }
        sM[e * NT + tid] = fmaf(Ii, R0, Up - Un);   // overwrite soc-prefix with base

        float In1 = (e < EE - 1) ? sIv[(e + 1) * NT + tid]
                                 : sIv[(tid < NT - 1) ? tid + 1 : NT - 1];
        bool last = (tid == NT - 1) && (e == EE - 1);
        float eps = (In1 - Ii) * C;           // dt = diff of I (per reference)
        float a  = last ? 1.f : 1.f - eps;
        float bb = last ? 0.f : eps * R1 * Ii;
        sPA[e * NT + tid] = At;               // exclusive intra-thread prefix
        sPB[e * NT + tid] = Bt;
        Bt = fmaf(a, Bt, bb);
        At = a * At;
    }

    // ---------- phase 4: block affine-pair scan (exclusive over threads) ----------
    float Ai = At, Bi = Bt;
    #pragma unroll
    for (int o = 1; o < 32; o <<= 1) {
        float pA = __shfl_up_sync(0xffffffffu, Ai, o);
        float pB = __shfl_up_sync(0xffffffffu, Bi, o);
        if (lane >= o) { Bi = fmaf(Ai, pB, Bi); Ai = Ai * pA; }
    }
    if (lane == 31) { sA[wid] = Ai; sB[wid] = Bi; }
    __syncthreads();
    if (tid < 32) {
        float vA = sA[tid], vB = sB[tid];
        #pragma unroll
        for (int o = 1; o < 32; o <<= 1) {
            float pA = __shfl_up_sync(0xffffffffu, vA, o);
            float pB = __shfl_up_sync(0xffffffffu, vB, o);
            if (lane >= o) { vB = fmaf(vA, pB, vB); vA = vA * pA; }
        }
        sA[tid] = vA; sB[tid] = vB;
    }
    __syncthreads();
    float offA = 1.f, offB = 0.f;
    if (wid > 0) { offA = sA[wid - 1]; offB = sB[wid - 1]; }
    float eA = __shfl_up_sync(0xffffffffu, Ai, 1);
    float eB = __shfl_up_sync(0xffffffffu, Bi, 1);
    if (lane == 0) { eA = 1.f; eB = 0.f; }
    const float GA = eA * offA;
    const float GB = fmaf(eA, offB, eB);
    const float U1t = fmaf(GA, sU10, GB);   // U1 entering this thread's chunk

    // ---------- phase 5: emit with float4 stores ----------
    float4* __restrict__ o4 = reinterpret_cast<float4*>(out + (size_t)b * TT + tid * EE);
    #pragma unroll
    for (int g = 0; g < 2; ++g) {
        float4 w;
        #pragma unroll
        for (int k = 0; k < 4; ++k) {
            int e = 4 * g + k;
            float u1 = fmaf(sPA[e * NT + tid], U1t, sPB[e * NT + tid]);
            (&w.x)[k] = sM[e * NT + tid] + u1;
        }
        o4[g] = w;
    }
}

extern "C" void kernel_launch(void* const* d_in, const int* in_sizes, int n_in,
                              void* d_out, int out_size)
{
    const float* X  = (const float*)d_in[0];
    const float* SC = (const float*)d_in[1];
    const float* W1 = (const float*)d_in[2];
    const float* b1 = (const float*)d_in[3];
    const float* W2 = (const float*)d_in[4];
    const float* b2 = (const float*)d_in[5];
    float* out = (float*)d_out;

    static bool attr_done = false;
    if (!attr_done) {
        cudaFuncSetAttribute(voltage_kernel,
                             cudaFuncAttributeMaxDynamicSharedMemorySize, SMEM_BYTES);
        attr_done = true;
    }

    int B = in_sizes[1] / 2;   // SC is (B, 2)
    voltage_kernel<<<B, NT, SMEM_BYTES>>>(X, SC, W1, b1, W2, b2, out);
}